// round 1
// baseline (speedup 1.0000x reference)
#include <cuda_runtime.h>
#include <cuda_bf16.h>

// Problem constants (fixed by setup_inputs)
#define BATCH   8
#define C_NEW   21
#define C_OLD   16
#define HW      262144          // 512*512 = 2^18
#define HW_BITS 18
#define NPIX    (BATCH * HW)    // 2,097,152

__device__ double   g_acc;
__device__ unsigned g_present;  // bit c set  <=>  class c present in masks (c in 1..20)

// ---------------------------------------------------------------------------
// Kernel 0: zero the accumulators (runs every graph replay -> deterministic)
// ---------------------------------------------------------------------------
__global__ void k_zero() {
    g_acc = 0.0;
    g_present = 0u;
}

// ---------------------------------------------------------------------------
// Kernel 1: scan masks -> present bitmask.  8 MB read, one atomicOr per warp.
// ---------------------------------------------------------------------------
__global__ void k_scan(const int* __restrict__ masks) {
    unsigned local = 0u;
    int stride = gridDim.x * blockDim.x;
    for (int i = blockIdx.x * blockDim.x + threadIdx.x; i < NPIX; i += stride) {
        int v = masks[i];
        if (v >= 1 && v < 32) local |= (1u << v);   // 0 excluded; 255 out of range
    }
    // warp-wide OR, one atomic per warp
    #pragma unroll
    for (int off = 16; off; off >>= 1)
        local |= __shfl_down_sync(0xffffffffu, local, off);
    if ((threadIdx.x & 31) == 0 && local)
        atomicOr(&g_present, local);
}

// ---------------------------------------------------------------------------
// Kernel 2: main fused loss. One thread per pixel; all channels in registers.
// ---------------------------------------------------------------------------
__global__ __launch_bounds__(256) void k_main(const float* __restrict__ inputs,
                                              const float* __restrict__ targets,
                                              const int*   __restrict__ masks) {
    int p  = blockIdx.x * 256 + threadIdx.x;      // pixel id, grid sized exactly
    int b  = p >> HW_BITS;
    int hw = p & (HW - 1);

    // ---- load all channels (coalesced 32-bit loads, high MLP) ----
    float x[C_NEW];
    {
        const float* base = inputs + (size_t)b * C_NEW * HW + hw;
        #pragma unroll
        for (int c = 0; c < C_NEW; ++c) x[c] = base[c * HW];
    }
    float t[C_OLD];
    {
        const float* base = targets + (size_t)b * C_OLD * HW + hw;
        #pragma unroll
        for (int c = 0; c < C_OLD; ++c) t[c] = base[c * HW];
    }
    int m = masks[p];
    unsigned pm = g_present;   // uniform across grid

    // ---- log_softmax over inputs (need lse only; out_c = x_c - lse) ----
    float mx = x[0];
    #pragma unroll
    for (int c = 1; c < C_NEW; ++c) mx = fmaxf(mx, x[c]);
    float s = 0.f;
    #pragma unroll
    for (int c = 0; c < C_NEW; ++c) s += __expf(x[c] - mx);
    float lse = mx + __logf(s);

    // ---- softmax over targets ----
    float mt = t[0];
    #pragma unroll
    for (int c = 1; c < C_OLD; ++c) mt = fmaxf(mt, t[c]);
    float st = 0.f;
    #pragma unroll
    for (int c = 0; c < C_OLD; ++c) st += __expf(t[c] - mt);
    float inv_st = __frcp_rn(st);
    float lab0   = __expf(t[0] - mt) * inv_st;

    // ---- select x[m] without dynamic register indexing ----
    float xm = 0.f;
    #pragma unroll
    for (int c = 0; c < C_NEW; ++c) xm = (c == m) ? x[c] : xm;

    // ---- per-pixel dot product sum_c outputs[c]*new_labels[c] ----
    float dot;
    if (m == 0 || m == 255) {
        dot = lab0 * (x[0] - lse);                       // bg: channel 0 survives
    } else if (m >= 1 && m <= 20 && ((pm >> m) & 1u)) {
        dot = lab0 * (xm - lse);                         // replaced one-hot term
    } else {
        dot = 0.f;
    }
    // non-present old-task channels keep their soft labels (uniform branch; empty
    // in the common case where every class 1..15 appears somewhere in masks)
    #pragma unroll
    for (int c = 1; c < C_OLD; ++c) {
        if (!((pm >> c) & 1u))
            dot += (x[c] - lse) * __expf(t[c] - mt) * inv_st;
    }

    // ---- block reduction -> one double atomic per block ----
    #pragma unroll
    for (int off = 16; off; off >>= 1)
        dot += __shfl_down_sync(0xffffffffu, dot, off);
    __shared__ float ws[8];
    if ((threadIdx.x & 31) == 0) ws[threadIdx.x >> 5] = dot;
    __syncthreads();
    if (threadIdx.x == 0) {
        float bsum = 0.f;
        #pragma unroll
        for (int i = 0; i < 8; ++i) bsum += ws[i];
        atomicAdd(&g_acc, (double)bsum);
    }
}

// ---------------------------------------------------------------------------
// Kernel 3: finalize scalar
// ---------------------------------------------------------------------------
__global__ void k_final(float* __restrict__ out) {
    out[0] = (float)(-g_acc / ((double)C_NEW * (double)NPIX));
}

extern "C" void kernel_launch(void* const* d_in, const int* in_sizes, int n_in,
                              void* d_out, int out_size) {
    const float* inputs  = (const float*)d_in[0];
    const float* targets = (const float*)d_in[1];
    const int*   masks   = (const int*)d_in[2];
    float*       out     = (float*)d_out;

    k_zero<<<1, 1>>>();
    k_scan<<<1024, 256>>>(masks);
    k_main<<<NPIX / 256, 256>>>(inputs, targets, masks);
    k_final<<<1, 1>>>(out);
}